// round 4
// baseline (speedup 1.0000x reference)
#include <cuda_runtime.h>
#include <math.h>

// Problem constants
#define B_ 4
#define T_ 2048
#define C_ 2048
#define H_ 16
#define DH 128
#define THREE_C (3 * C_)

// Scratch (device globals — allocation-free)
__device__ float g_qkv[(size_t)B_ * T_ * THREE_C];  // 192 MiB
__device__ float g_y[(size_t)B_ * T_ * C_];         // 64 MiB

// ---------------------------------------------------------------------------
// SGEMM: C = A(MxK) * B(KxN) + bias(N), row-major, fp32.
// 128x128 block tile, BK=8, 256 threads, 8x8 per thread (4x4 quads).
// Requires M%128==0, N%128==0, K%8==0.
// ---------------------------------------------------------------------------
__global__ __launch_bounds__(256, 2)
void sgemm_bias_kernel(const float* __restrict__ A, const float* __restrict__ Bm,
                       const float* __restrict__ bias, float* __restrict__ Cm,
                       int M, int N, int K)
{
    const int BK = 8;
    __shared__ float As[BK][128];
    __shared__ float Bs[BK][128];

    const int tid = threadIdx.x;
    const int tr = tid >> 4;        // 0..15
    const int tc = tid & 15;        // 0..15
    const int rowBase = blockIdx.y * 128;
    const int colBase = blockIdx.x * 128;

    const int aRow = tid >> 1;            // 0..127
    const int aCol = (tid & 1) * 4;       // 0 or 4
    const int bRow = tid >> 5;            // 0..7
    const int bCol = (tid & 31) * 4;      // 0..124

    const float* Aptr = A + (size_t)(rowBase + aRow) * K + aCol;
    const float* Bptr = Bm + (size_t)bRow * N + colBase + bCol;

    float acc[8][8];
#pragma unroll
    for (int i = 0; i < 8; i++)
#pragma unroll
        for (int j = 0; j < 8; j++) acc[i][j] = 0.f;

    for (int k0 = 0; k0 < K; k0 += BK) {
        float4 a4 = *(const float4*)(Aptr + k0);
        As[aCol + 0][aRow] = a4.x;
        As[aCol + 1][aRow] = a4.y;
        As[aCol + 2][aRow] = a4.z;
        As[aCol + 3][aRow] = a4.w;
        *(float4*)&Bs[bRow][bCol] = *(const float4*)(Bptr + (size_t)k0 * N);
        __syncthreads();

#pragma unroll
        for (int k = 0; k < BK; k++) {
            float ra[8], rb[8];
            *(float4*)&ra[0] = *(const float4*)&As[k][tr * 4];
            *(float4*)&ra[4] = *(const float4*)&As[k][64 + tr * 4];
            *(float4*)&rb[0] = *(const float4*)&Bs[k][tc * 4];
            *(float4*)&rb[4] = *(const float4*)&Bs[k][64 + tc * 4];
#pragma unroll
            for (int i = 0; i < 8; i++)
#pragma unroll
                for (int j = 0; j < 8; j++)
                    acc[i][j] = fmaf(ra[i], rb[j], acc[i][j]);
        }
        __syncthreads();
    }

    // Epilogue: + bias, write two float4 per owned row
    float4 bb0 = *(const float4*)&bias[colBase + tc * 4];
    float4 bb1 = *(const float4*)&bias[colBase + 64 + tc * 4];
#pragma unroll
    for (int i = 0; i < 8; i++) {
        int r = rowBase + ((i < 4) ? (tr * 4 + i) : (64 + tr * 4 + i - 4));
        float4 o0, o1;
        o0.x = acc[i][0] + bb0.x; o0.y = acc[i][1] + bb0.y;
        o0.z = acc[i][2] + bb0.z; o0.w = acc[i][3] + bb0.w;
        o1.x = acc[i][4] + bb1.x; o1.y = acc[i][5] + bb1.y;
        o1.z = acc[i][6] + bb1.z; o1.w = acc[i][7] + bb1.w;
        *(float4*)(Cm + (size_t)r * N + colBase + tc * 4) = o0;
        *(float4*)(Cm + (size_t)r * N + colBase + 64 + tc * 4) = o1;
    }
}

// ---------------------------------------------------------------------------
// RoPE in-place on q and k slices of g_qkv. Rotation over the FULL C dim:
// pair p uses channels (2p, 2p+1), inv_freq = theta^(-2p/C), angle = t*inv.
// Cody-Waite reduction keeps sincos accurate for angles up to ~2047 rad.
// ---------------------------------------------------------------------------
__global__ void rope_kernel(float* __restrict__ qkv)
{
    const size_t NP = (size_t)B_ * T_ * (C_ / 2);
    size_t idx = (size_t)blockIdx.x * blockDim.x + threadIdx.x;
    if (idx >= 2 * NP) return;
    int sel = (idx >= NP) ? 1 : 0;   // 0 = q, 1 = k
    size_t r = sel ? (idx - NP) : idx;
    int p = (int)(r % (C_ / 2));
    size_t bt = r / (C_ / 2);
    int t = (int)(bt % T_);

    float e = (float)(2 * p) * (1.0f / (float)C_);
    float inv = expf(-9.210340371976184f * e);   // theta^(-2p/C), ln(1e4)
    float ang = (float)t * inv;

    // reduce ang mod 2*pi (Cody-Waite, 2 terms)
    float kq = rintf(ang * 0.15915494309189535f);
    float rr = fmaf(-kq, 6.28318548202514648f, ang);
    rr = fmaf(-kq, -1.7484556000744083e-7f, rr);
    float s, c;
    sincosf(rr, &s, &c);

    float* ptr = qkv + bt * (size_t)THREE_C + (size_t)sel * C_ + 2 * p;
    float2 v = *(float2*)ptr;
    float2 o;
    o.x = v.x * c - v.y * s;
    o.y = v.x * s + v.y * c;
    *(float2*)ptr = o;
}

// ---------------------------------------------------------------------------
// Flash attention, fp32, causal. BQ=64 q rows, BKV=64 kv rows, dh=128.
// 256 threads. Thread (sq=tid/16, sk=tid%16):
//   phase 1 owns S rows sq*4+{0..3}, cols sk+16*{0..3}
//   phase 2 owns O rows sq*4+{0..3}, d cols sk*4+{0..3} and 64+sk*4+{0..3}
// Row softmax stats reduced across the 16-lane sk group via shfl_xor.
// ---------------------------------------------------------------------------
#define BQ 64
#define BKV 64
#define PAD 132
#define ATTN_SMEM_FLOATS (3 * BQ * PAD + BQ * BKV)

__global__ __launch_bounds__(256, 1)
void attn_kernel(const float* __restrict__ qkv, float* __restrict__ y)
{
    extern __shared__ float sm[];
    float* Qs = sm;                       // 64 x PAD
    float* Ks = Qs + BQ * PAD;            // 64 x PAD
    float* Vs = Ks + BKV * PAD;           // 64 x PAD
    float* Ps = Vs + BKV * PAD;           // 64 x 64

    const int qt = blockIdx.x;
    const int h  = blockIdx.y;
    const int b  = blockIdx.z;
    const int q0 = qt * BQ;
    const int tid = threadIdx.x;
    const int sq = tid >> 4;
    const int sk = tid & 15;
    const float SCALE = 0.08838834764831845f;  // 1/sqrt(128)

    // Load Q tile (pre-scaled)
    {
        int lane = tid & 31, rofs = tid >> 5;
#pragma unroll
        for (int it = 0; it < 8; it++) {
            int row = rofs + it * 8;
            size_t g = ((size_t)(b * T_ + q0 + row)) * THREE_C + h * DH + lane * 4;
            float4 v = *(const float4*)(qkv + g);
            float* dst = &Qs[row * PAD + lane * 4];
            dst[0] = v.x * SCALE; dst[1] = v.y * SCALE;
            dst[2] = v.z * SCALE; dst[3] = v.w * SCALE;
        }
    }

    float m[4], l[4], O[4][8];
#pragma unroll
    for (int i = 0; i < 4; i++) {
        m[i] = -INFINITY; l[i] = 0.f;
#pragma unroll
        for (int j = 0; j < 8; j++) O[i][j] = 0.f;
    }

    for (int jt = 0; jt <= qt; jt++) {
        const int k0 = jt * BKV;
        __syncthreads();   // prior P*V done reading Ps/Vs
        // Load K, V tiles
        {
            int lane = tid & 31, rofs = tid >> 5;
#pragma unroll
            for (int it = 0; it < 8; it++) {
                int row = rofs + it * 8;
                size_t gk = ((size_t)(b * T_ + k0 + row)) * THREE_C + C_ + h * DH + lane * 4;
                *(float4*)&Ks[row * PAD + lane * 4] = *(const float4*)(qkv + gk);
                *(float4*)&Vs[row * PAD + lane * 4] = *(const float4*)(qkv + gk + C_);
            }
        }
        __syncthreads();

        // S = (Q*scale) @ K^T
        float Sv[4][4];
#pragma unroll
        for (int i = 0; i < 4; i++)
#pragma unroll
            for (int j = 0; j < 4; j++) Sv[i][j] = 0.f;

#pragma unroll 8
        for (int dd = 0; dd < DH; dd += 4) {
            float4 q4[4], k4[4];
#pragma unroll
            for (int i = 0; i < 4; i++)
                q4[i] = *(const float4*)&Qs[(sq * 4 + i) * PAD + dd];
#pragma unroll
            for (int j = 0; j < 4; j++)
                k4[j] = *(const float4*)&Ks[(sk + 16 * j) * PAD + dd];
#pragma unroll
            for (int i = 0; i < 4; i++)
#pragma unroll
                for (int j = 0; j < 4; j++) {
                    Sv[i][j] = fmaf(q4[i].x, k4[j].x, Sv[i][j]);
                    Sv[i][j] = fmaf(q4[i].y, k4[j].y, Sv[i][j]);
                    Sv[i][j] = fmaf(q4[i].z, k4[j].z, Sv[i][j]);
                    Sv[i][j] = fmaf(q4[i].w, k4[j].w, Sv[i][j]);
                }
        }

        // Causal mask on the diagonal tile
        if (jt == qt) {
#pragma unroll
            for (int i = 0; i < 4; i++) {
                int qg = sq * 4 + i;
#pragma unroll
                for (int j = 0; j < 4; j++)
                    if (sk + 16 * j > qg) Sv[i][j] = -INFINITY;
            }
        }

        // Online softmax update + write P to smem
#pragma unroll
        for (int i = 0; i < 4; i++) {
            float mt = fmaxf(fmaxf(Sv[i][0], Sv[i][1]), fmaxf(Sv[i][2], Sv[i][3]));
#pragma unroll
            for (int o = 8; o >= 1; o >>= 1)
                mt = fmaxf(mt, __shfl_xor_sync(0xffffffffu, mt, o));
            float mn = fmaxf(m[i], mt);
            float corr = expf(m[i] - mn);   // m=-inf -> 0
            float ps[4], rs = 0.f;
#pragma unroll
            for (int j = 0; j < 4; j++) {
                ps[j] = expf(Sv[i][j] - mn);
                rs += ps[j];
            }
#pragma unroll
            for (int o = 8; o >= 1; o >>= 1)
                rs += __shfl_xor_sync(0xffffffffu, rs, o);
            l[i] = l[i] * corr + rs;
            m[i] = mn;
#pragma unroll
            for (int j = 0; j < 8; j++) O[i][j] *= corr;
#pragma unroll
            for (int j = 0; j < 4; j++)
                Ps[(sq * 4 + i) * BKV + sk + 16 * j] = ps[j];
        }
        __syncthreads();

        // O += P @ V
#pragma unroll 2
        for (int kk = 0; kk < BKV; kk += 4) {
            float pr[4][4];
#pragma unroll
            for (int i = 0; i < 4; i++)
                *(float4*)pr[i] = *(const float4*)&Ps[(sq * 4 + i) * BKV + kk];
#pragma unroll
            for (int t4 = 0; t4 < 4; t4++) {
                float4 va = *(const float4*)&Vs[(kk + t4) * PAD + sk * 4];
                float4 vb = *(const float4*)&Vs[(kk + t4) * PAD + 64 + sk * 4];
#pragma unroll
                for (int i = 0; i < 4; i++) {
                    float p = pr[i][t4];
                    O[i][0] = fmaf(p, va.x, O[i][0]);
                    O[i][1] = fmaf(p, va.y, O[i][1]);
                    O[i][2] = fmaf(p, va.z, O[i][2]);
                    O[i][3] = fmaf(p, va.w, O[i][3]);
                    O[i][4] = fmaf(p, vb.x, O[i][4]);
                    O[i][5] = fmaf(p, vb.y, O[i][5]);
                    O[i][6] = fmaf(p, vb.z, O[i][6]);
                    O[i][7] = fmaf(p, vb.w, O[i][7]);
                }
            }
        }
    }

    // Normalize and write y (B,T,C) with c = h*DH + d
#pragma unroll
    for (int i = 0; i < 4; i++) {
        float inv_l = 1.f / l[i];
        size_t g = ((size_t)(b * T_ + q0 + sq * 4 + i)) * C_ + h * DH;
        float4 o0, o1;
        o0.x = O[i][0] * inv_l; o0.y = O[i][1] * inv_l;
        o0.z = O[i][2] * inv_l; o0.w = O[i][3] * inv_l;
        o1.x = O[i][4] * inv_l; o1.y = O[i][5] * inv_l;
        o1.z = O[i][6] * inv_l; o1.w = O[i][7] * inv_l;
        *(float4*)(y + g + sk * 4) = o0;
        *(float4*)(y + g + 64 + sk * 4) = o1;
    }
}

// ---------------------------------------------------------------------------
// Launch
// ---------------------------------------------------------------------------
extern "C" void kernel_launch(void* const* d_in, const int* in_sizes, int n_in,
                              void* d_out, int out_size)
{
    (void)in_sizes; (void)n_in; (void)out_size;
    const float* x      = (const float*)d_in[0];
    const float* w_qkv  = (const float*)d_in[1];
    const float* b_qkv  = (const float*)d_in[2];
    const float* w_proj = (const float*)d_in[3];
    const float* b_proj = (const float*)d_in[4];
    float* out = (float*)d_out;

    void* p_qkv = nullptr;
    void* p_y = nullptr;
    cudaGetSymbolAddress(&p_qkv, g_qkv);
    cudaGetSymbolAddress(&p_y, g_y);
    float* qkv = (float*)p_qkv;
    float* y   = (float*)p_y;

    const int M = B_ * T_;  // 8192

    // 1) QKV = x @ w_qkv + b_qkv
    {
        dim3 grid(3 * C_ / 128, M / 128);
        sgemm_bias_kernel<<<grid, 256>>>(x, w_qkv, b_qkv, qkv, M, 3 * C_, C_);
    }

    // 2) RoPE in-place on q and k
    {
        size_t total = 2ull * B_ * T_ * (C_ / 2);
        int threads = 256;
        int blocks = (int)((total + threads - 1) / threads);
        rope_kernel<<<blocks, threads>>>(qkv);
    }

    // 3) Causal flash attention -> y (B,T,C)
    {
        static int smem_set = 0;
        size_t smem = ATTN_SMEM_FLOATS * sizeof(float);
        cudaFuncSetAttribute(attn_kernel, cudaFuncAttributeMaxDynamicSharedMemorySize,
                             (int)smem);
        (void)smem_set;
        dim3 grid(T_ / BQ, H_, B_);
        attn_kernel<<<grid, 256, smem>>>(qkv, y);
    }

    // 4) out = y @ w_proj + b_proj
    {
        dim3 grid(C_ / 128, M / 128);
        sgemm_bias_kernel<<<grid, 256>>>(y, w_proj, b_proj, out, M, C_, C_);
    }
}

// round 5
// speedup vs baseline: 1.0004x; 1.0004x over previous
#include <cuda_runtime.h>
#include <math.h>

// Problem constants
#define B_ 4
#define T_ 2048
#define C_ 2048
#define H_ 16
#define DH 128
#define THREE_C (3 * C_)

// Scratch (device globals — allocation-free)
__device__ float g_qkv[(size_t)B_ * T_ * THREE_C];  // 192 MiB
__device__ float g_y[(size_t)B_ * T_ * C_];         // 64 MiB

// ---------------------------------------------------------------------------
// SGEMM: C = A(MxK) * B(KxN) + bias(N), row-major, fp32.
// 128x128 block tile, BK=8, 256 threads, 8x8 per thread (4x4 quads).
// Requires M%128==0, N%128==0, K%8==0.
// ---------------------------------------------------------------------------
__global__ __launch_bounds__(256, 2)
void sgemm_bias_kernel(const float* __restrict__ A, const float* __restrict__ Bm,
                       const float* __restrict__ bias, float* __restrict__ Cm,
                       int M, int N, int K)
{
    const int BK = 8;
    __shared__ float As[BK][128];
    __shared__ float Bs[BK][128];

    const int tid = threadIdx.x;
    const int tr = tid >> 4;        // 0..15
    const int tc = tid & 15;        // 0..15
    const int rowBase = blockIdx.y * 128;
    const int colBase = blockIdx.x * 128;

    const int aRow = tid >> 1;            // 0..127
    const int aCol = (tid & 1) * 4;       // 0 or 4
    const int bRow = tid >> 5;            // 0..7
    const int bCol = (tid & 31) * 4;      // 0..124

    const float* Aptr = A + (size_t)(rowBase + aRow) * K + aCol;
    const float* Bptr = Bm + (size_t)bRow * N + colBase + bCol;

    float acc[8][8];
#pragma unroll
    for (int i = 0; i < 8; i++)
#pragma unroll
        for (int j = 0; j < 8; j++) acc[i][j] = 0.f;

    for (int k0 = 0; k0 < K; k0 += BK) {
        float4 a4 = *(const float4*)(Aptr + k0);
        As[aCol + 0][aRow] = a4.x;
        As[aCol + 1][aRow] = a4.y;
        As[aCol + 2][aRow] = a4.z;
        As[aCol + 3][aRow] = a4.w;
        *(float4*)&Bs[bRow][bCol] = *(const float4*)(Bptr + (size_t)k0 * N);
        __syncthreads();

#pragma unroll
        for (int k = 0; k < BK; k++) {
            float ra[8], rb[8];
            *(float4*)&ra[0] = *(const float4*)&As[k][tr * 4];
            *(float4*)&ra[4] = *(const float4*)&As[k][64 + tr * 4];
            *(float4*)&rb[0] = *(const float4*)&Bs[k][tc * 4];
            *(float4*)&rb[4] = *(const float4*)&Bs[k][64 + tc * 4];
#pragma unroll
            for (int i = 0; i < 8; i++)
#pragma unroll
                for (int j = 0; j < 8; j++)
                    acc[i][j] = fmaf(ra[i], rb[j], acc[i][j]);
        }
        __syncthreads();
    }

    // Epilogue: + bias, write two float4 per owned row
    float4 bb0 = *(const float4*)&bias[colBase + tc * 4];
    float4 bb1 = *(const float4*)&bias[colBase + 64 + tc * 4];
#pragma unroll
    for (int i = 0; i < 8; i++) {
        int r = rowBase + ((i < 4) ? (tr * 4 + i) : (64 + tr * 4 + i - 4));
        float4 o0, o1;
        o0.x = acc[i][0] + bb0.x; o0.y = acc[i][1] + bb0.y;
        o0.z = acc[i][2] + bb0.z; o0.w = acc[i][3] + bb0.w;
        o1.x = acc[i][4] + bb1.x; o1.y = acc[i][5] + bb1.y;
        o1.z = acc[i][6] + bb1.z; o1.w = acc[i][7] + bb1.w;
        *(float4*)(Cm + (size_t)r * N + colBase + tc * 4) = o0;
        *(float4*)(Cm + (size_t)r * N + colBase + 64 + tc * 4) = o1;
    }
}

// ---------------------------------------------------------------------------
// RoPE in-place on q and k slices of g_qkv. Rotation over the FULL C dim:
// pair p uses channels (2p, 2p+1), inv_freq = theta^(-2p/C), angle = t*inv.
// Cody-Waite reduction keeps sincos accurate for angles up to ~2047 rad.
// ---------------------------------------------------------------------------
__global__ void rope_kernel(float* __restrict__ qkv)
{
    const size_t NP = (size_t)B_ * T_ * (C_ / 2);
    size_t idx = (size_t)blockIdx.x * blockDim.x + threadIdx.x;
    if (idx >= 2 * NP) return;
    int sel = (idx >= NP) ? 1 : 0;   // 0 = q, 1 = k
    size_t r = sel ? (idx - NP) : idx;
    int p = (int)(r % (C_ / 2));
    size_t bt = r / (C_ / 2);
    int t = (int)(bt % T_);

    float e = (float)(2 * p) * (1.0f / (float)C_);
    float inv = expf(-9.210340371976184f * e);   // theta^(-2p/C), ln(1e4)
    float ang = (float)t * inv;

    // reduce ang mod 2*pi (Cody-Waite, 2 terms)
    float kq = rintf(ang * 0.15915494309189535f);
    float rr = fmaf(-kq, 6.28318548202514648f, ang);
    rr = fmaf(-kq, -1.7484556000744083e-7f, rr);
    float s, c;
    sincosf(rr, &s, &c);

    float* ptr = qkv + bt * (size_t)THREE_C + (size_t)sel * C_ + 2 * p;
    float2 v = *(float2*)ptr;
    float2 o;
    o.x = v.x * c - v.y * s;
    o.y = v.x * s + v.y * c;
    *(float2*)ptr = o;
}

// ---------------------------------------------------------------------------
// Flash attention, fp32, causal. BQ=64 q rows, BKV=64 kv rows, dh=128.
// 256 threads. Thread (sq=tid/16, sk=tid%16):
//   phase 1 owns S rows sq*4+{0..3}, cols sk+16*{0..3}
//   phase 2 owns O rows sq*4+{0..3}, d cols sk*4+{0..3} and 64+sk*4+{0..3}
// Row softmax stats reduced across the 16-lane sk group via shfl_xor.
// ---------------------------------------------------------------------------
#define BQ 64
#define BKV 64
#define PAD 132
#define ATTN_SMEM_FLOATS (3 * BQ * PAD + BQ * BKV)

__global__ __launch_bounds__(256, 1)
void attn_kernel(const float* __restrict__ qkv, float* __restrict__ y)
{
    extern __shared__ float sm[];
    float* Qs = sm;                       // 64 x PAD
    float* Ks = Qs + BQ * PAD;            // 64 x PAD
    float* Vs = Ks + BKV * PAD;           // 64 x PAD
    float* Ps = Vs + BKV * PAD;           // 64 x 64

    const int qt = blockIdx.x;
    const int h  = blockIdx.y;
    const int b  = blockIdx.z;
    const int q0 = qt * BQ;
    const int tid = threadIdx.x;
    const int sq = tid >> 4;
    const int sk = tid & 15;
    const float SCALE = 0.08838834764831845f;  // 1/sqrt(128)

    // Load Q tile (pre-scaled)
    {
        int lane = tid & 31, rofs = tid >> 5;
#pragma unroll
        for (int it = 0; it < 8; it++) {
            int row = rofs + it * 8;
            size_t g = ((size_t)(b * T_ + q0 + row)) * THREE_C + h * DH + lane * 4;
            float4 v = *(const float4*)(qkv + g);
            float* dst = &Qs[row * PAD + lane * 4];
            dst[0] = v.x * SCALE; dst[1] = v.y * SCALE;
            dst[2] = v.z * SCALE; dst[3] = v.w * SCALE;
        }
    }

    float m[4], l[4], O[4][8];
#pragma unroll
    for (int i = 0; i < 4; i++) {
        m[i] = -INFINITY; l[i] = 0.f;
#pragma unroll
        for (int j = 0; j < 8; j++) O[i][j] = 0.f;
    }

    for (int jt = 0; jt <= qt; jt++) {
        const int k0 = jt * BKV;
        __syncthreads();   // prior P*V done reading Ps/Vs
        // Load K, V tiles
        {
            int lane = tid & 31, rofs = tid >> 5;
#pragma unroll
            for (int it = 0; it < 8; it++) {
                int row = rofs + it * 8;
                size_t gk = ((size_t)(b * T_ + k0 + row)) * THREE_C + C_ + h * DH + lane * 4;
                *(float4*)&Ks[row * PAD + lane * 4] = *(const float4*)(qkv + gk);
                *(float4*)&Vs[row * PAD + lane * 4] = *(const float4*)(qkv + gk + C_);
            }
        }
        __syncthreads();

        // S = (Q*scale) @ K^T
        float Sv[4][4];
#pragma unroll
        for (int i = 0; i < 4; i++)
#pragma unroll
            for (int j = 0; j < 4; j++) Sv[i][j] = 0.f;

#pragma unroll 8
        for (int dd = 0; dd < DH; dd += 4) {
            float4 q4[4], k4[4];
#pragma unroll
            for (int i = 0; i < 4; i++)
                q4[i] = *(const float4*)&Qs[(sq * 4 + i) * PAD + dd];
#pragma unroll
            for (int j = 0; j < 4; j++)
                k4[j] = *(const float4*)&Ks[(sk + 16 * j) * PAD + dd];
#pragma unroll
            for (int i = 0; i < 4; i++)
#pragma unroll
                for (int j = 0; j < 4; j++) {
                    Sv[i][j] = fmaf(q4[i].x, k4[j].x, Sv[i][j]);
                    Sv[i][j] = fmaf(q4[i].y, k4[j].y, Sv[i][j]);
                    Sv[i][j] = fmaf(q4[i].z, k4[j].z, Sv[i][j]);
                    Sv[i][j] = fmaf(q4[i].w, k4[j].w, Sv[i][j]);
                }
        }

        // Causal mask on the diagonal tile
        if (jt == qt) {
#pragma unroll
            for (int i = 0; i < 4; i++) {
                int qg = sq * 4 + i;
#pragma unroll
                for (int j = 0; j < 4; j++)
                    if (sk + 16 * j > qg) Sv[i][j] = -INFINITY;
            }
        }

        // Online softmax update + write P to smem
#pragma unroll
        for (int i = 0; i < 4; i++) {
            float mt = fmaxf(fmaxf(Sv[i][0], Sv[i][1]), fmaxf(Sv[i][2], Sv[i][3]));
#pragma unroll
            for (int o = 8; o >= 1; o >>= 1)
                mt = fmaxf(mt, __shfl_xor_sync(0xffffffffu, mt, o));
            float mn = fmaxf(m[i], mt);
            float corr = expf(m[i] - mn);   // m=-inf -> 0
            float ps[4], rs = 0.f;
#pragma unroll
            for (int j = 0; j < 4; j++) {
                ps[j] = expf(Sv[i][j] - mn);
                rs += ps[j];
            }
#pragma unroll
            for (int o = 8; o >= 1; o >>= 1)
                rs += __shfl_xor_sync(0xffffffffu, rs, o);
            l[i] = l[i] * corr + rs;
            m[i] = mn;
#pragma unroll
            for (int j = 0; j < 8; j++) O[i][j] *= corr;
#pragma unroll
            for (int j = 0; j < 4; j++)
                Ps[(sq * 4 + i) * BKV + sk + 16 * j] = ps[j];
        }
        __syncthreads();

        // O += P @ V
#pragma unroll 2
        for (int kk = 0; kk < BKV; kk += 4) {
            float pr[4][4];
#pragma unroll
            for (int i = 0; i < 4; i++)
                *(float4*)pr[i] = *(const float4*)&Ps[(sq * 4 + i) * BKV + kk];
#pragma unroll
            for (int t4 = 0; t4 < 4; t4++) {
                float4 va = *(const float4*)&Vs[(kk + t4) * PAD + sk * 4];
                float4 vb = *(const float4*)&Vs[(kk + t4) * PAD + 64 + sk * 4];
#pragma unroll
                for (int i = 0; i < 4; i++) {
                    float p = pr[i][t4];
                    O[i][0] = fmaf(p, va.x, O[i][0]);
                    O[i][1] = fmaf(p, va.y, O[i][1]);
                    O[i][2] = fmaf(p, va.z, O[i][2]);
                    O[i][3] = fmaf(p, va.w, O[i][3]);
                    O[i][4] = fmaf(p, vb.x, O[i][4]);
                    O[i][5] = fmaf(p, vb.y, O[i][5]);
                    O[i][6] = fmaf(p, vb.z, O[i][6]);
                    O[i][7] = fmaf(p, vb.w, O[i][7]);
                }
            }
        }
    }

    // Normalize and write y (B,T,C) with c = h*DH + d
#pragma unroll
    for (int i = 0; i < 4; i++) {
        float inv_l = 1.f / l[i];
        size_t g = ((size_t)(b * T_ + q0 + sq * 4 + i)) * C_ + h * DH;
        float4 o0, o1;
        o0.x = O[i][0] * inv_l; o0.y = O[i][1] * inv_l;
        o0.z = O[i][2] * inv_l; o0.w = O[i][3] * inv_l;
        o1.x = O[i][4] * inv_l; o1.y = O[i][5] * inv_l;
        o1.z = O[i][6] * inv_l; o1.w = O[i][7] * inv_l;
        *(float4*)(y + g + sk * 4) = o0;
        *(float4*)(y + g + 64 + sk * 4) = o1;
    }
}

// ---------------------------------------------------------------------------
// Launch
// ---------------------------------------------------------------------------
extern "C" void kernel_launch(void* const* d_in, const int* in_sizes, int n_in,
                              void* d_out, int out_size)
{
    (void)in_sizes; (void)n_in; (void)out_size;
    const float* x      = (const float*)d_in[0];
    const float* w_qkv  = (const float*)d_in[1];
    const float* b_qkv  = (const float*)d_in[2];
    const float* w_proj = (const float*)d_in[3];
    const float* b_proj = (const float*)d_in[4];
    float* out = (float*)d_out;

    void* p_qkv = nullptr;
    void* p_y = nullptr;
    cudaGetSymbolAddress(&p_qkv, g_qkv);
    cudaGetSymbolAddress(&p_y, g_y);
    float* qkv = (float*)p_qkv;
    float* y   = (float*)p_y;

    const int M = B_ * T_;  // 8192

    // 1) QKV = x @ w_qkv + b_qkv
    {
        dim3 grid(3 * C_ / 128, M / 128);
        sgemm_bias_kernel<<<grid, 256>>>(x, w_qkv, b_qkv, qkv, M, 3 * C_, C_);
    }

    // 2) RoPE in-place on q and k
    {
        size_t total = 2ull * B_ * T_ * (C_ / 2);
        int threads = 256;
        int blocks = (int)((total + threads - 1) / threads);
        rope_kernel<<<blocks, threads>>>(qkv);
    }

    // 3) Causal flash attention -> y (B,T,C)
    {
        static int smem_set = 0;
        size_t smem = ATTN_SMEM_FLOATS * sizeof(float);
        cudaFuncSetAttribute(attn_kernel, cudaFuncAttributeMaxDynamicSharedMemorySize,
                             (int)smem);
        (void)smem_set;
        dim3 grid(T_ / BQ, H_, B_);
        attn_kernel<<<grid, 256, smem>>>(qkv, y);
    }

    // 4) out = y @ w_proj + b_proj
    {
        dim3 grid(C_ / 128, M / 128);
        sgemm_bias_kernel<<<grid, 256>>>(y, w_proj, b_proj, out, M, C_, C_);
    }
}

// round 6
// speedup vs baseline: 1.0009x; 1.0004x over previous
#include <cuda_runtime.h>
#include <math.h>

// Problem constants
#define B_ 4
#define T_ 2048
#define C_ 2048
#define H_ 16
#define DH 128
#define THREE_C (3 * C_)

// Scratch (device globals — allocation-free)
__device__ float g_qkv[(size_t)B_ * T_ * THREE_C];  // 192 MiB
__device__ float g_y[(size_t)B_ * T_ * C_];         // 64 MiB

// ---------------------------------------------------------------------------
// SGEMM: C = A(MxK) * B(KxN) + bias(N), row-major, fp32.
// 128x128 block tile, BK=8, 256 threads, 8x8 per thread (4x4 quads).
// Requires M%128==0, N%128==0, K%8==0.
// ---------------------------------------------------------------------------
__global__ __launch_bounds__(256, 2)
void sgemm_bias_kernel(const float* __restrict__ A, const float* __restrict__ Bm,
                       const float* __restrict__ bias, float* __restrict__ Cm,
                       int M, int N, int K)
{
    const int BK = 8;
    __shared__ float As[BK][128];
    __shared__ float Bs[BK][128];

    const int tid = threadIdx.x;
    const int tr = tid >> 4;        // 0..15
    const int tc = tid & 15;        // 0..15
    const int rowBase = blockIdx.y * 128;
    const int colBase = blockIdx.x * 128;

    const int aRow = tid >> 1;            // 0..127
    const int aCol = (tid & 1) * 4;       // 0 or 4
    const int bRow = tid >> 5;            // 0..7
    const int bCol = (tid & 31) * 4;      // 0..124

    const float* Aptr = A + (size_t)(rowBase + aRow) * K + aCol;
    const float* Bptr = Bm + (size_t)bRow * N + colBase + bCol;

    float acc[8][8];
#pragma unroll
    for (int i = 0; i < 8; i++)
#pragma unroll
        for (int j = 0; j < 8; j++) acc[i][j] = 0.f;

    for (int k0 = 0; k0 < K; k0 += BK) {
        float4 a4 = *(const float4*)(Aptr + k0);
        As[aCol + 0][aRow] = a4.x;
        As[aCol + 1][aRow] = a4.y;
        As[aCol + 2][aRow] = a4.z;
        As[aCol + 3][aRow] = a4.w;
        *(float4*)&Bs[bRow][bCol] = *(const float4*)(Bptr + (size_t)k0 * N);
        __syncthreads();

#pragma unroll
        for (int k = 0; k < BK; k++) {
            float ra[8], rb[8];
            *(float4*)&ra[0] = *(const float4*)&As[k][tr * 4];
            *(float4*)&ra[4] = *(const float4*)&As[k][64 + tr * 4];
            *(float4*)&rb[0] = *(const float4*)&Bs[k][tc * 4];
            *(float4*)&rb[4] = *(const float4*)&Bs[k][64 + tc * 4];
#pragma unroll
            for (int i = 0; i < 8; i++)
#pragma unroll
                for (int j = 0; j < 8; j++)
                    acc[i][j] = fmaf(ra[i], rb[j], acc[i][j]);
        }
        __syncthreads();
    }

    // Epilogue: + bias, write two float4 per owned row
    float4 bb0 = *(const float4*)&bias[colBase + tc * 4];
    float4 bb1 = *(const float4*)&bias[colBase + 64 + tc * 4];
#pragma unroll
    for (int i = 0; i < 8; i++) {
        int r = rowBase + ((i < 4) ? (tr * 4 + i) : (64 + tr * 4 + i - 4));
        float4 o0, o1;
        o0.x = acc[i][0] + bb0.x; o0.y = acc[i][1] + bb0.y;
        o0.z = acc[i][2] + bb0.z; o0.w = acc[i][3] + bb0.w;
        o1.x = acc[i][4] + bb1.x; o1.y = acc[i][5] + bb1.y;
        o1.z = acc[i][6] + bb1.z; o1.w = acc[i][7] + bb1.w;
        *(float4*)(Cm + (size_t)r * N + colBase + tc * 4) = o0;
        *(float4*)(Cm + (size_t)r * N + colBase + 64 + tc * 4) = o1;
    }
}

// ---------------------------------------------------------------------------
// RoPE in-place on q and k slices of g_qkv. Rotation over the FULL C dim:
// pair p uses channels (2p, 2p+1), inv_freq = theta^(-2p/C), angle = t*inv.
// Cody-Waite reduction keeps sincos accurate for angles up to ~2047 rad.
// ---------------------------------------------------------------------------
__global__ void rope_kernel(float* __restrict__ qkv)
{
    const size_t NP = (size_t)B_ * T_ * (C_ / 2);
    size_t idx = (size_t)blockIdx.x * blockDim.x + threadIdx.x;
    if (idx >= 2 * NP) return;
    int sel = (idx >= NP) ? 1 : 0;   // 0 = q, 1 = k
    size_t r = sel ? (idx - NP) : idx;
    int p = (int)(r % (C_ / 2));
    size_t bt = r / (C_ / 2);
    int t = (int)(bt % T_);

    float e = (float)(2 * p) * (1.0f / (float)C_);
    float inv = expf(-9.210340371976184f * e);   // theta^(-2p/C), ln(1e4)
    float ang = (float)t * inv;

    // reduce ang mod 2*pi (Cody-Waite, 2 terms)
    float kq = rintf(ang * 0.15915494309189535f);
    float rr = fmaf(-kq, 6.28318548202514648f, ang);
    rr = fmaf(-kq, -1.7484556000744083e-7f, rr);
    float s, c;
    sincosf(rr, &s, &c);

    float* ptr = qkv + bt * (size_t)THREE_C + (size_t)sel * C_ + 2 * p;
    float2 v = *(float2*)ptr;
    float2 o;
    o.x = v.x * c - v.y * s;
    o.y = v.x * s + v.y * c;
    *(float2*)ptr = o;
}

// ---------------------------------------------------------------------------
// Flash attention, fp32, causal. BQ=64 q rows, BKV=64 kv rows, dh=128.
// 256 threads. Thread (sq=tid/16, sk=tid%16):
//   phase 1 owns S rows sq*4+{0..3}, cols sk+16*{0..3}
//   phase 2 owns O rows sq*4+{0..3}, d cols sk*4+{0..3} and 64+sk*4+{0..3}
// Row softmax stats reduced across the 16-lane sk group via shfl_xor.
// ---------------------------------------------------------------------------
#define BQ 64
#define BKV 64
#define PAD 132
#define ATTN_SMEM_FLOATS (3 * BQ * PAD + BQ * BKV)

__global__ __launch_bounds__(256, 1)
void attn_kernel(const float* __restrict__ qkv, float* __restrict__ y)
{
    extern __shared__ float sm[];
    float* Qs = sm;                       // 64 x PAD
    float* Ks = Qs + BQ * PAD;            // 64 x PAD
    float* Vs = Ks + BKV * PAD;           // 64 x PAD
    float* Ps = Vs + BKV * PAD;           // 64 x 64

    const int qt = blockIdx.x;
    const int h  = blockIdx.y;
    const int b  = blockIdx.z;
    const int q0 = qt * BQ;
    const int tid = threadIdx.x;
    const int sq = tid >> 4;
    const int sk = tid & 15;
    const float SCALE = 0.08838834764831845f;  // 1/sqrt(128)

    // Load Q tile (pre-scaled)
    {
        int lane = tid & 31, rofs = tid >> 5;
#pragma unroll
        for (int it = 0; it < 8; it++) {
            int row = rofs + it * 8;
            size_t g = ((size_t)(b * T_ + q0 + row)) * THREE_C + h * DH + lane * 4;
            float4 v = *(const float4*)(qkv + g);
            float* dst = &Qs[row * PAD + lane * 4];
            dst[0] = v.x * SCALE; dst[1] = v.y * SCALE;
            dst[2] = v.z * SCALE; dst[3] = v.w * SCALE;
        }
    }

    float m[4], l[4], O[4][8];
#pragma unroll
    for (int i = 0; i < 4; i++) {
        m[i] = -INFINITY; l[i] = 0.f;
#pragma unroll
        for (int j = 0; j < 8; j++) O[i][j] = 0.f;
    }

    for (int jt = 0; jt <= qt; jt++) {
        const int k0 = jt * BKV;
        __syncthreads();   // prior P*V done reading Ps/Vs
        // Load K, V tiles
        {
            int lane = tid & 31, rofs = tid >> 5;
#pragma unroll
            for (int it = 0; it < 8; it++) {
                int row = rofs + it * 8;
                size_t gk = ((size_t)(b * T_ + k0 + row)) * THREE_C + C_ + h * DH + lane * 4;
                *(float4*)&Ks[row * PAD + lane * 4] = *(const float4*)(qkv + gk);
                *(float4*)&Vs[row * PAD + lane * 4] = *(const float4*)(qkv + gk + C_);
            }
        }
        __syncthreads();

        // S = (Q*scale) @ K^T
        float Sv[4][4];
#pragma unroll
        for (int i = 0; i < 4; i++)
#pragma unroll
            for (int j = 0; j < 4; j++) Sv[i][j] = 0.f;

#pragma unroll 8
        for (int dd = 0; dd < DH; dd += 4) {
            float4 q4[4], k4[4];
#pragma unroll
            for (int i = 0; i < 4; i++)
                q4[i] = *(const float4*)&Qs[(sq * 4 + i) * PAD + dd];
#pragma unroll
            for (int j = 0; j < 4; j++)
                k4[j] = *(const float4*)&Ks[(sk + 16 * j) * PAD + dd];
#pragma unroll
            for (int i = 0; i < 4; i++)
#pragma unroll
                for (int j = 0; j < 4; j++) {
                    Sv[i][j] = fmaf(q4[i].x, k4[j].x, Sv[i][j]);
                    Sv[i][j] = fmaf(q4[i].y, k4[j].y, Sv[i][j]);
                    Sv[i][j] = fmaf(q4[i].z, k4[j].z, Sv[i][j]);
                    Sv[i][j] = fmaf(q4[i].w, k4[j].w, Sv[i][j]);
                }
        }

        // Causal mask on the diagonal tile
        if (jt == qt) {
#pragma unroll
            for (int i = 0; i < 4; i++) {
                int qg = sq * 4 + i;
#pragma unroll
                for (int j = 0; j < 4; j++)
                    if (sk + 16 * j > qg) Sv[i][j] = -INFINITY;
            }
        }

        // Online softmax update + write P to smem
#pragma unroll
        for (int i = 0; i < 4; i++) {
            float mt = fmaxf(fmaxf(Sv[i][0], Sv[i][1]), fmaxf(Sv[i][2], Sv[i][3]));
#pragma unroll
            for (int o = 8; o >= 1; o >>= 1)
                mt = fmaxf(mt, __shfl_xor_sync(0xffffffffu, mt, o));
            float mn = fmaxf(m[i], mt);
            float corr = expf(m[i] - mn);   // m=-inf -> 0
            float ps[4], rs = 0.f;
#pragma unroll
            for (int j = 0; j < 4; j++) {
                ps[j] = expf(Sv[i][j] - mn);
                rs += ps[j];
            }
#pragma unroll
            for (int o = 8; o >= 1; o >>= 1)
                rs += __shfl_xor_sync(0xffffffffu, rs, o);
            l[i] = l[i] * corr + rs;
            m[i] = mn;
#pragma unroll
            for (int j = 0; j < 8; j++) O[i][j] *= corr;
#pragma unroll
            for (int j = 0; j < 4; j++)
                Ps[(sq * 4 + i) * BKV + sk + 16 * j] = ps[j];
        }
        __syncthreads();

        // O += P @ V
#pragma unroll 2
        for (int kk = 0; kk < BKV; kk += 4) {
            float pr[4][4];
#pragma unroll
            for (int i = 0; i < 4; i++)
                *(float4*)pr[i] = *(const float4*)&Ps[(sq * 4 + i) * BKV + kk];
#pragma unroll
            for (int t4 = 0; t4 < 4; t4++) {
                float4 va = *(const float4*)&Vs[(kk + t4) * PAD + sk * 4];
                float4 vb = *(const float4*)&Vs[(kk + t4) * PAD + 64 + sk * 4];
#pragma unroll
                for (int i = 0; i < 4; i++) {
                    float p = pr[i][t4];
                    O[i][0] = fmaf(p, va.x, O[i][0]);
                    O[i][1] = fmaf(p, va.y, O[i][1]);
                    O[i][2] = fmaf(p, va.z, O[i][2]);
                    O[i][3] = fmaf(p, va.w, O[i][3]);
                    O[i][4] = fmaf(p, vb.x, O[i][4]);
                    O[i][5] = fmaf(p, vb.y, O[i][5]);
                    O[i][6] = fmaf(p, vb.z, O[i][6]);
                    O[i][7] = fmaf(p, vb.w, O[i][7]);
                }
            }
        }
    }

    // Normalize and write y (B,T,C) with c = h*DH + d
#pragma unroll
    for (int i = 0; i < 4; i++) {
        float inv_l = 1.f / l[i];
        size_t g = ((size_t)(b * T_ + q0 + sq * 4 + i)) * C_ + h * DH;
        float4 o0, o1;
        o0.x = O[i][0] * inv_l; o0.y = O[i][1] * inv_l;
        o0.z = O[i][2] * inv_l; o0.w = O[i][3] * inv_l;
        o1.x = O[i][4] * inv_l; o1.y = O[i][5] * inv_l;
        o1.z = O[i][6] * inv_l; o1.w = O[i][7] * inv_l;
        *(float4*)(y + g + sk * 4) = o0;
        *(float4*)(y + g + 64 + sk * 4) = o1;
    }
}

// ---------------------------------------------------------------------------
// Launch
// ---------------------------------------------------------------------------
extern "C" void kernel_launch(void* const* d_in, const int* in_sizes, int n_in,
                              void* d_out, int out_size)
{
    (void)in_sizes; (void)n_in; (void)out_size;
    const float* x      = (const float*)d_in[0];
    const float* w_qkv  = (const float*)d_in[1];
    const float* b_qkv  = (const float*)d_in[2];
    const float* w_proj = (const float*)d_in[3];
    const float* b_proj = (const float*)d_in[4];
    float* out = (float*)d_out;

    void* p_qkv = nullptr;
    void* p_y = nullptr;
    cudaGetSymbolAddress(&p_qkv, g_qkv);
    cudaGetSymbolAddress(&p_y, g_y);
    float* qkv = (float*)p_qkv;
    float* y   = (float*)p_y;

    const int M = B_ * T_;  // 8192

    // 1) QKV = x @ w_qkv + b_qkv
    {
        dim3 grid(3 * C_ / 128, M / 128);
        sgemm_bias_kernel<<<grid, 256>>>(x, w_qkv, b_qkv, qkv, M, 3 * C_, C_);
    }

    // 2) RoPE in-place on q and k
    {
        size_t total = 2ull * B_ * T_ * (C_ / 2);
        int threads = 256;
        int blocks = (int)((total + threads - 1) / threads);
        rope_kernel<<<blocks, threads>>>(qkv);
    }

    // 3) Causal flash attention -> y (B,T,C)
    {
        static int smem_set = 0;
        size_t smem = ATTN_SMEM_FLOATS * sizeof(float);
        cudaFuncSetAttribute(attn_kernel, cudaFuncAttributeMaxDynamicSharedMemorySize,
                             (int)smem);
        (void)smem_set;
        dim3 grid(T_ / BQ, H_, B_);
        attn_kernel<<<grid, 256, smem>>>(qkv, y);
    }

    // 4) out = y @ w_proj + b_proj
    {
        dim3 grid(C_ / 128, M / 128);
        sgemm_bias_kernel<<<grid, 256>>>(y, w_proj, b_proj, out, M, C_, C_);
    }
}